// round 3
// baseline (speedup 1.0000x reference)
#include <cuda_runtime.h>
#include <cuda_fp16.h>
#include <math.h>

#define NMAX 100000
#define EMAX 1600000
#define HID 64

// ---------------- scratch (static device globals; no allocation) ----------------
__device__ int     g_deg[NMAX];
__device__ int     g_rowptr[NMAX + 1];
__device__ int     g_fill[NMAX];
__device__ int     g_bsums[256];
__device__ float   g_inv[NMAX];
__device__ int     g_col[EMAX];
__device__ __half2 g_xh[(size_t)NMAX * 32];
__device__ __half2 g_h1h[(size_t)NMAX * 32];
__device__ __half2 g_h2h[(size_t)NMAX * 32];
__device__ int     g_is64;

// ---------------- init: zero deg + detect edge_index dtype ----------------
__global__ void k_init(int* __restrict__ deg, int n, const unsigned int* __restrict__ p) {
    int i = blockIdx.x * blockDim.x + threadIdx.x;
    if (i < n) deg[i] = 0;
    if (i == 0) {
        int ok = 1;
        #pragma unroll
        for (int j = 0; j < 64; j++)
            if (p[2 * j + 1] != 0u) ok = 0;
        g_is64 = ok;
    }
}

__device__ __forceinline__ int load_idx(const void* base, long long i, int is64) {
    if (is64) return (int)((const long long*)base)[i];
    return ((const int*)base)[i];
}

// ---------------- CSR build ----------------
__global__ void k_count(const void* __restrict__ ei, int* __restrict__ deg, int e) {
    int i = blockIdx.x * blockDim.x + threadIdx.x;
    int is64 = g_is64;
    if (i < e) {
        int d = load_idx(ei, (long long)e + i, is64);
        atomicAdd(&deg[d], 1);
    }
}

__global__ void k_scan1(const int* __restrict__ deg, int* __restrict__ rowptr,
                        int* __restrict__ bsums, int n) {
    __shared__ int warp_tot[32];
    int i = blockIdx.x * 1024 + threadIdx.x;
    int lane = threadIdx.x & 31, wid = threadIdx.x >> 5;
    int v = (i < n) ? deg[i] : 0;
    int x = v;
    #pragma unroll
    for (int d = 1; d < 32; d <<= 1) {
        int y = __shfl_up_sync(0xffffffffu, x, d);
        if (lane >= d) x += y;
    }
    if (lane == 31) warp_tot[wid] = x;
    __syncthreads();
    if (wid == 0) {
        int t = warp_tot[lane];
        #pragma unroll
        for (int d = 1; d < 32; d <<= 1) {
            int y = __shfl_up_sync(0xffffffffu, t, d);
            if (lane >= d) t += y;
        }
        warp_tot[lane] = t;
    }
    __syncthreads();
    int base = (wid > 0) ? warp_tot[wid - 1] : 0;
    if (i < n) rowptr[i] = base + x - v;
    if (threadIdx.x == 0) bsums[blockIdx.x] = warp_tot[31];
}

// parallel exclusive scan of <=128 block sums (single 128-thread block)
__global__ void k_scan2(int* __restrict__ bsums, int nb) {
    __shared__ int wsum[4];
    int t = threadIdx.x;
    int lane = t & 31, wid = t >> 5;
    int v = (t < nb) ? bsums[t] : 0;
    int x = v;
    #pragma unroll
    for (int d = 1; d < 32; d <<= 1) {
        int y = __shfl_up_sync(0xffffffffu, x, d);
        if (lane >= d) x += y;
    }
    if (lane == 31) wsum[wid] = x;
    __syncthreads();
    int add = 0;
    #pragma unroll
    for (int w = 0; w < 4; w++) if (w < wid) add += wsum[w];
    if (t < nb) bsums[t] = add + x - v;
}

__global__ void k_scan3(int* __restrict__ rowptr, const int* __restrict__ bsums,
                        const int* __restrict__ deg, int* __restrict__ fill,
                        float* __restrict__ inv, int n, int e) {
    int i = blockIdx.x * blockDim.x + threadIdx.x;
    if (i < n) {
        int rp = rowptr[i] + bsums[i >> 10];
        rowptr[i] = rp;
        fill[i] = rp;
        int d = deg[i];
        inv[i] = 1.0f / (float)max(d, 1);
    }
    if (i == 0) rowptr[n] = e;
}

__global__ void k_scatter(const void* __restrict__ ei, int* __restrict__ fill,
                          int* __restrict__ col, int e) {
    int i = blockIdx.x * blockDim.x + threadIdx.x;
    int is64 = g_is64;
    if (i < e) {
        int d = load_idx(ei, (long long)e + i, is64);
        int s = load_idx(ei, (long long)i, is64);
        int p = atomicAdd(&fill[d], 1);
        col[p] = s;
    }
}

// ---------------- convert x (fp32) -> half2 ----------------
__global__ void k_cvt(const float2* __restrict__ x, __half2* __restrict__ xh, int n32) {
    int i = blockIdx.x * blockDim.x + threadIdx.x;
    if (i < n32) {
        float2 v = x[i];
        xh[i] = __floats2half2_rn(v.x, v.y);
    }
}

// ---------------- FUSED: per-block gather-mean + dual-GEMM + bias + ReLU ----------------
// Block = 64 nodes. Phase 1: warps gather neighbor sums -> sA packed (mean, hin) f32x2.
// Phase 2: f32x2 FFMA tile GEMM against packed (Wl, Wr). Epilogue: relu(accx+accy+b) -> fp16.
#define GEMM_SMEM (2 * 64 * 64 * 8 + 256)

__global__ void __launch_bounds__(256) k_fused(
    const __half2* __restrict__ xin,
    const float* __restrict__ Wl, const float* __restrict__ Wr,
    const float* __restrict__ bias, __half2* __restrict__ houth,
    const int* __restrict__ rowptr, const int* __restrict__ col,
    const float* __restrict__ inv, int n) {
    extern __shared__ float2 smem[];
    float2* sA = smem;               // [64 nodes][64 k] packed (mean_k, hin_k)
    float2* sW = smem + 64 * 64;     // [64 k][64 o]   packed (Wl, Wr)
    float*  sB = (float*)(smem + 2 * 64 * 64);

    int t = threadIdx.x;
    int lane = t & 31, wid = t >> 5;
    int node0 = blockIdx.x * 64;

    // weights + bias
    for (int idx = t; idx < 64 * 64; idx += 256)
        sW[idx] = make_float2(Wl[idx], Wr[idx]);
    if (t < 64) sB[t] = bias[t];

    // gather: each of 8 warps handles 8 nodes
    float4* sA4 = reinterpret_cast<float4*>(sA);
    for (int nn = wid; nn < 64; nn += 8) {
        int node = node0 + nn;
        float ax = 0.f, ay = 0.f, hx = 0.f, hy = 0.f, iv = 0.f;
        if (node < n) {
            int s = rowptr[node], e = rowptr[node + 1];
            int i = s;
            for (; i + 8 <= e; i += 8) {
                int c0 = __ldg(&col[i + 0]); int c1 = __ldg(&col[i + 1]);
                int c2 = __ldg(&col[i + 2]); int c3 = __ldg(&col[i + 3]);
                int c4 = __ldg(&col[i + 4]); int c5 = __ldg(&col[i + 5]);
                int c6 = __ldg(&col[i + 6]); int c7 = __ldg(&col[i + 7]);
                float2 v0 = __half22float2(xin[(size_t)c0 * 32 + lane]);
                float2 v1 = __half22float2(xin[(size_t)c1 * 32 + lane]);
                float2 v2 = __half22float2(xin[(size_t)c2 * 32 + lane]);
                float2 v3 = __half22float2(xin[(size_t)c3 * 32 + lane]);
                float2 v4 = __half22float2(xin[(size_t)c4 * 32 + lane]);
                float2 v5 = __half22float2(xin[(size_t)c5 * 32 + lane]);
                float2 v6 = __half22float2(xin[(size_t)c6 * 32 + lane]);
                float2 v7 = __half22float2(xin[(size_t)c7 * 32 + lane]);
                ax += ((v0.x + v1.x) + (v2.x + v3.x)) + ((v4.x + v5.x) + (v6.x + v7.x));
                ay += ((v0.y + v1.y) + (v2.y + v3.y)) + ((v4.y + v5.y) + (v6.y + v7.y));
            }
            for (; i < e; i++) {
                int c0 = __ldg(&col[i]);
                float2 v0 = __half22float2(xin[(size_t)c0 * 32 + lane]);
                ax += v0.x; ay += v0.y;
            }
            float2 hv = __half22float2(xin[(size_t)node * 32 + lane]);
            hx = hv.x; hy = hv.y;
            iv = inv[node];
        }
        // k = 2*lane -> (mean, hin); k = 2*lane+1 -> (mean, hin)
        sA4[nn * 32 + lane] = make_float4(ax * iv, hx, ay * iv, hy);
    }
    __syncthreads();

    int tn = t >> 4;  // node group: nodes tn, tn+16, tn+32, tn+48
    int to = t & 15;  // out group:  outs  to, to+16, to+32, to+48

    unsigned long long acc[4][4];
    #pragma unroll
    for (int i = 0; i < 4; i++)
        #pragma unroll
        for (int j = 0; j < 4; j++) acc[i][j] = 0ULL;

    const unsigned long long* A64 = reinterpret_cast<const unsigned long long*>(sA);
    const unsigned long long* W64 = reinterpret_cast<const unsigned long long*>(sW);

    #pragma unroll 4
    for (int k = 0; k < 64; k++) {
        unsigned long long a[4], w[4];
        #pragma unroll
        for (int i = 0; i < 4; i++) a[i] = A64[(tn + 16 * i) * 64 + k];
        #pragma unroll
        for (int j = 0; j < 4; j++) w[j] = W64[k * 64 + to + 16 * j];
        #pragma unroll
        for (int i = 0; i < 4; i++)
            #pragma unroll
            for (int j = 0; j < 4; j++)
                asm("fma.rn.f32x2 %0, %1, %2, %0;"
                    : "+l"(acc[i][j]) : "l"(a[i]), "l"(w[j]));
    }
    __syncthreads();

    // epilogue staged through smem (reuse sW), coalesced 16B stores
    __half* sH = (__half*)sW;   // [64 nodes][64 o]
    #pragma unroll
    for (int i = 0; i < 4; i++) {
        #pragma unroll
        for (int j = 0; j < 4; j++) {
            int o = to + 16 * j;
            unsigned long long v = acc[i][j];
            float2 r = *reinterpret_cast<float2*>(&v);
            float out = fmaxf(r.x + r.y + sB[o], 0.f);
            sH[(tn + 16 * i) * 64 + o] = __float2half_rn(out);
        }
    }
    __syncthreads();

    const int4* src = reinterpret_cast<const int4*>(sH);
    int4* dst = reinterpret_cast<int4*>(houth + (size_t)node0 * 32);
    for (int idx = t; idx < 512; idx += 256) {
        int node = node0 + (idx >> 3);
        if (node < n) dst[idx] = src[idx];
    }
}

// ---------------- classifier + log_softmax: one warp per node ----------------
__global__ void k_cls(const __half2* __restrict__ h, const float* __restrict__ Wc,
                      const float* __restrict__ bc, float* __restrict__ out, int n) {
    __shared__ float sW[640];
    __shared__ float sb[16];
    int t = threadIdx.x;
    for (int idx = t; idx < 640; idx += 256) sW[idx] = Wc[idx];
    if (t < 10) sb[t] = bc[t];
    __syncthreads();
    int w = (blockIdx.x * blockDim.x + t) >> 5;
    int lane = t & 31;
    if (w >= n) return;
    float2 hv = __half22float2(h[(size_t)w * 32 + lane]);
    float v[10];
    #pragma unroll
    for (int c = 0; c < 10; c++) {
        float p = hv.x * sW[(2 * lane) * 10 + c] + hv.y * sW[(2 * lane + 1) * 10 + c];
        #pragma unroll
        for (int d = 16; d > 0; d >>= 1) p += __shfl_xor_sync(0xffffffffu, p, d);
        v[c] = p + sb[c];
    }
    float m = v[0];
    #pragma unroll
    for (int c = 1; c < 10; c++) m = fmaxf(m, v[c]);
    float s = 0.f;
    #pragma unroll
    for (int c = 0; c < 10; c++) s += expf(v[c] - m);
    float lse = m + logf(s);
    if (lane == 0) {
        #pragma unroll
        for (int c = 0; c < 10; c++) out[(size_t)w * 10 + c] = v[c] - lse;
    }
}

// ---------------- launch ----------------
extern "C" void kernel_launch(void* const* d_in, const int* in_sizes, int n_in,
                              void* d_out, int out_size) {
    const float* x = (const float*)d_in[0];
    const void*  ei = d_in[1];
    int n = in_sizes[0] / HID;
    int e = in_sizes[1] / 2;

    const float* Wl1 = (const float*)d_in[2];
    const float* bl1 = (const float*)d_in[3];
    const float* Wr1 = (const float*)d_in[4];
    const float* Wl2 = (const float*)d_in[5];
    const float* bl2 = (const float*)d_in[6];
    const float* Wr2 = (const float*)d_in[7];
    const float* Wl3 = (const float*)d_in[8];
    const float* bl3 = (const float*)d_in[9];
    const float* Wr3 = (const float*)d_in[10];
    const float* Wc  = (const float*)d_in[11];
    const float* bc  = (const float*)d_in[12];
    float* out = (float*)d_out;

    int *deg, *rowptr, *fill, *bsums, *col;
    float *inv;
    __half2 *xh, *h1h, *h2h;
    cudaGetSymbolAddress((void**)&deg, g_deg);
    cudaGetSymbolAddress((void**)&rowptr, g_rowptr);
    cudaGetSymbolAddress((void**)&fill, g_fill);
    cudaGetSymbolAddress((void**)&bsums, g_bsums);
    cudaGetSymbolAddress((void**)&col, g_col);
    cudaGetSymbolAddress((void**)&inv, g_inv);
    cudaGetSymbolAddress((void**)&xh, g_xh);
    cudaGetSymbolAddress((void**)&h1h, g_h1h);
    cudaGetSymbolAddress((void**)&h2h, g_h2h);

    cudaFuncSetAttribute(k_fused, cudaFuncAttributeMaxDynamicSharedMemorySize, GEMM_SMEM);

    // CSR build + fp16 conversion of x
    k_init<<<(n + 255) / 256, 256>>>(deg, n, (const unsigned int*)ei);
    k_count<<<(e + 255) / 256, 256>>>(ei, deg, e);
    int nb = (n + 1023) / 1024;
    k_scan1<<<nb, 1024>>>(deg, rowptr, bsums, n);
    k_scan2<<<1, 128>>>(bsums, nb);
    k_scan3<<<(n + 255) / 256, 256>>>(rowptr, bsums, deg, fill, inv, n, e);
    k_scatter<<<(e + 255) / 256, 256>>>(ei, fill, col, e);
    k_cvt<<<(n * 32 + 255) / 256, 256>>>((const float2*)x, xh, n * 32);

    int fusedBlocks = (n + 63) / 64;

    k_fused<<<fusedBlocks, 256, GEMM_SMEM>>>(xh,  Wl1, Wr1, bl1, h1h, rowptr, col, inv, n);
    k_fused<<<fusedBlocks, 256, GEMM_SMEM>>>(h1h, Wl2, Wr2, bl2, h2h, rowptr, col, inv, n);
    k_fused<<<fusedBlocks, 256, GEMM_SMEM>>>(h2h, Wl3, Wr3, bl3, h1h, rowptr, col, inv, n);
    k_cls<<<(n * 32 + 255) / 256, 256>>>(h1h, Wc, bc, out, n);
}

// round 4
// speedup vs baseline: 1.6135x; 1.6135x over previous
#include <cuda_runtime.h>
#include <cuda_fp16.h>
#include <math.h>

#define NMAX 100000
#define EMAX 1600000
#define HID 64

// ---------------- scratch (static device globals; no allocation) ----------------
__device__ int     g_deg[NMAX];
__device__ int     g_rowptr[NMAX + 1];
__device__ int     g_fill[NMAX];
__device__ int     g_bsums[256];
__device__ float   g_inv[NMAX];
__device__ int     g_col[EMAX];
__device__ __half2 g_xh[(size_t)NMAX * 32];
__device__ __half2 g_meanh[(size_t)NMAX * 32];
__device__ __half2 g_h1h[(size_t)NMAX * 32];
__device__ __half2 g_h2h[(size_t)NMAX * 32];
__device__ __half  g_wf16[3 * 64 * 128];   // [layer][n(64)][k(128)]  k-contig
__device__ int     g_is64;

// ---------------- init: zero deg + detect edge_index dtype ----------------
__global__ void k_init(int* __restrict__ deg, int n, const unsigned int* __restrict__ p) {
    int i = blockIdx.x * blockDim.x + threadIdx.x;
    if (i < n) deg[i] = 0;
    if (i == 0) {
        int ok = 1;
        #pragma unroll
        for (int j = 0; j < 64; j++)
            if (p[2 * j + 1] != 0u) ok = 0;
        g_is64 = ok;
    }
}

__device__ __forceinline__ int load_idx(const void* base, long long i, int is64) {
    if (is64) return (int)((const long long*)base)[i];
    return ((const int*)base)[i];
}

// ---------------- CSR build ----------------
__global__ void k_count(const void* __restrict__ ei, int* __restrict__ deg, int e) {
    int i = blockIdx.x * blockDim.x + threadIdx.x;
    int is64 = g_is64;
    if (i < e) {
        int d = load_idx(ei, (long long)e + i, is64);
        atomicAdd(&deg[d], 1);
    }
}

__global__ void k_scan1(const int* __restrict__ deg, int* __restrict__ rowptr,
                        int* __restrict__ bsums, int n) {
    __shared__ int warp_tot[32];
    int i = blockIdx.x * 1024 + threadIdx.x;
    int lane = threadIdx.x & 31, wid = threadIdx.x >> 5;
    int v = (i < n) ? deg[i] : 0;
    int x = v;
    #pragma unroll
    for (int d = 1; d < 32; d <<= 1) {
        int y = __shfl_up_sync(0xffffffffu, x, d);
        if (lane >= d) x += y;
    }
    if (lane == 31) warp_tot[wid] = x;
    __syncthreads();
    if (wid == 0) {
        int t = warp_tot[lane];
        #pragma unroll
        for (int d = 1; d < 32; d <<= 1) {
            int y = __shfl_up_sync(0xffffffffu, t, d);
            if (lane >= d) t += y;
        }
        warp_tot[lane] = t;
    }
    __syncthreads();
    int base = (wid > 0) ? warp_tot[wid - 1] : 0;
    if (i < n) rowptr[i] = base + x - v;
    if (threadIdx.x == 0) bsums[blockIdx.x] = warp_tot[31];
}

// parallel exclusive scan of <=128 block sums
__global__ void k_scan2(int* __restrict__ bsums, int nb) {
    __shared__ int wsum[4];
    int t = threadIdx.x;
    int lane = t & 31, wid = t >> 5;
    int v = (t < nb) ? bsums[t] : 0;
    int x = v;
    #pragma unroll
    for (int d = 1; d < 32; d <<= 1) {
        int y = __shfl_up_sync(0xffffffffu, x, d);
        if (lane >= d) x += y;
    }
    if (lane == 31) wsum[wid] = x;
    __syncthreads();
    int add = 0;
    #pragma unroll
    for (int w = 0; w < 4; w++) if (w < wid) add += wsum[w];
    if (t < nb) bsums[t] = add + x - v;
}

__global__ void k_scan3(int* __restrict__ rowptr, const int* __restrict__ bsums,
                        const int* __restrict__ deg, int* __restrict__ fill,
                        float* __restrict__ inv, int n, int e) {
    int i = blockIdx.x * blockDim.x + threadIdx.x;
    if (i < n) {
        int rp = rowptr[i] + bsums[i >> 10];
        rowptr[i] = rp;
        fill[i] = rp;
        int d = deg[i];
        inv[i] = 1.0f / (float)max(d, 1);
    }
    if (i == 0) rowptr[n] = e;
}

__global__ void k_scatter(const void* __restrict__ ei, int* __restrict__ fill,
                          int* __restrict__ col, int e) {
    int i = blockIdx.x * blockDim.x + threadIdx.x;
    int is64 = g_is64;
    if (i < e) {
        int d = load_idx(ei, (long long)e + i, is64);
        int s = load_idx(ei, (long long)i, is64);
        int p = atomicAdd(&fill[d], 1);
        col[p] = s;
    }
}

// ---------------- convert x (fp32) -> half2 ----------------
__global__ void k_cvt(const float2* __restrict__ x, __half2* __restrict__ xh, int n32) {
    int i = blockIdx.x * blockDim.x + threadIdx.x;
    if (i < n32) {
        float2 v = x[i];
        xh[i] = __floats2half2_rn(v.x, v.y);
    }
}

// ---------------- weight prep: [Wl;Wr] fp32 -> fp16  [layer][n][k] ----------------
__global__ void k_wprep(const float* __restrict__ Wl1, const float* __restrict__ Wr1,
                        const float* __restrict__ Wl2, const float* __restrict__ Wr2,
                        const float* __restrict__ Wl3, const float* __restrict__ Wr3,
                        __half* __restrict__ wf) {
    int i = blockIdx.x * blockDim.x + threadIdx.x;
    if (i >= 3 * 64 * 128) return;
    int layer = i >> 13;
    int rem = i & 8191;
    int nIdx = rem >> 7;
    int k = rem & 127;
    const float* Wl = (layer == 0) ? Wl1 : (layer == 1) ? Wl2 : Wl3;
    const float* Wr = (layer == 0) ? Wr1 : (layer == 1) ? Wr2 : Wr3;
    float v = (k < 64) ? Wl[k * 64 + nIdx] : Wr[(k - 64) * 64 + nIdx];
    wf[i] = __float2half_rn(v);
}

// ---------------- mean aggregation: one warp per node, half2 gather ----------------
__global__ void k_agg(const __half2* __restrict__ x, __half2* __restrict__ mean,
                      const int* __restrict__ rowptr, const int* __restrict__ col,
                      const float* __restrict__ inv, int n) {
    int w = (blockIdx.x * blockDim.x + threadIdx.x) >> 5;
    int lane = threadIdx.x & 31;
    if (w >= n) return;
    int s = rowptr[w], e = rowptr[w + 1];
    float ax = 0.f, ay = 0.f;
    int i = s;
    for (; i + 4 <= e; i += 4) {
        int s0 = __ldg(&col[i + 0]);
        int s1 = __ldg(&col[i + 1]);
        int s2 = __ldg(&col[i + 2]);
        int s3 = __ldg(&col[i + 3]);
        float2 v0 = __half22float2(x[(size_t)s0 * 32 + lane]);
        float2 v1 = __half22float2(x[(size_t)s1 * 32 + lane]);
        float2 v2 = __half22float2(x[(size_t)s2 * 32 + lane]);
        float2 v3 = __half22float2(x[(size_t)s3 * 32 + lane]);
        ax += (v0.x + v1.x) + (v2.x + v3.x);
        ay += (v0.y + v1.y) + (v2.y + v3.y);
    }
    for (; i < e; i++) {
        int s0 = __ldg(&col[i]);
        float2 v0 = __half22float2(x[(size_t)s0 * 32 + lane]);
        ax += v0.x; ay += v0.y;
    }
    float iv = inv[w];
    mean[(size_t)w * 32 + lane] = __floats2half2_rn(ax * iv, ay * iv);
}

// ---------------- tensor-core dual GEMM + bias + ReLU ----------------
// A = [mean || hin]  (128 nodes x K=128 fp16), B = [Wl;Wr] as sW[n][k] fp16.
// mma.sync m16n8k16 fp16 -> fp32 accum. K padded to 136 halves in smem.
#define KPAD 136
#define GEMM_SMEM ((128 * KPAD + 64 * KPAD) * 2 + 256)

__device__ __forceinline__ void ldsm_x4(unsigned& r0, unsigned& r1, unsigned& r2, unsigned& r3, unsigned addr) {
    asm volatile("ldmatrix.sync.aligned.m8n8.x4.shared.b16 {%0,%1,%2,%3}, [%4];"
                 : "=r"(r0), "=r"(r1), "=r"(r2), "=r"(r3) : "r"(addr));
}
__device__ __forceinline__ void ldsm_x2(unsigned& r0, unsigned& r1, unsigned addr) {
    asm volatile("ldmatrix.sync.aligned.m8n8.x2.shared.b16 {%0,%1}, [%2];"
                 : "=r"(r0), "=r"(r1) : "r"(addr));
}

__global__ void __launch_bounds__(256) k_gemm(
    const __half2* __restrict__ meanh, const __half2* __restrict__ hinh,
    const __half* __restrict__ Wf, const float* __restrict__ bias,
    __half2* __restrict__ houth, int n) {
    extern __shared__ __half smem[];
    __half* sA = smem;                 // [128][KPAD]
    __half* sW = smem + 128 * KPAD;    // [64][KPAD]
    float*  sB = (float*)(sW + 64 * KPAD);

    int t = threadIdx.x;
    int lane = t & 31, wid = t >> 5;
    int node0 = blockIdx.x * 128;

    // load A: rows = nodes, k 0..63 = mean, 64..127 = hin  (int4 = 8 halves)
    const int4* mean4 = reinterpret_cast<const int4*>(meanh);
    const int4* hin4 = reinterpret_cast<const int4*>(hinh);
    int4* sA4 = reinterpret_cast<int4*>(sA);
    #pragma unroll
    for (int idx = t; idx < 128 * 16; idx += 256) {
        int nn = idx >> 4, j = idx & 15;
        int node = node0 + nn;
        int4 v = make_int4(0, 0, 0, 0);
        if (node < n) v = (j < 8) ? mean4[(size_t)node * 8 + j] : hin4[(size_t)node * 8 + (j - 8)];
        sA4[nn * (KPAD / 8) + j] = v;
    }
    // load W tile
    const int4* w4 = reinterpret_cast<const int4*>(Wf);
    int4* sW4 = reinterpret_cast<int4*>(sW);
    #pragma unroll
    for (int idx = t; idx < 64 * 16; idx += 256) {
        int nn = idx >> 4, j = idx & 15;
        sW4[nn * (KPAD / 8) + j] = w4[idx];
    }
    if (t < 64) sB[t] = bias[t];
    __syncthreads();

    unsigned sAaddr = (unsigned)__cvta_generic_to_shared(sA);
    unsigned sWaddr = (unsigned)__cvta_generic_to_shared(sW);

    int m0 = wid * 16;

    // per-lane ldmatrix source addresses
    int q = lane >> 3, r = lane & 7;
    unsigned aBase = sAaddr + (unsigned)(((m0 + r + ((q & 1) << 3)) * KPAD + ((q >> 1) << 3)) * 2);
    int br = lane & 15;
    unsigned bBase = sWaddr + (unsigned)((((br & 7) * KPAD) + ((br >> 3) << 3)) * 2);

    float acc[8][4];
    #pragma unroll
    for (int nn = 0; nn < 8; nn++)
        #pragma unroll
        for (int j = 0; j < 4; j++) acc[nn][j] = 0.f;

    #pragma unroll
    for (int kk = 0; kk < 8; kk++) {
        unsigned a0, a1, a2, a3;
        ldsm_x4(a0, a1, a2, a3, aBase + kk * 32);
        #pragma unroll
        for (int nn = 0; nn < 8; nn++) {
            unsigned b0, b1;
            ldsm_x2(b0, b1, bBase + (unsigned)((nn * 8 * KPAD + kk * 16) * 2));
            asm volatile(
                "mma.sync.aligned.m16n8k16.row.col.f32.f16.f16.f32 "
                "{%0,%1,%2,%3}, {%4,%5,%6,%7}, {%8,%9}, {%0,%1,%2,%3};"
                : "+f"(acc[nn][0]), "+f"(acc[nn][1]), "+f"(acc[nn][2]), "+f"(acc[nn][3])
                : "r"(a0), "r"(a1), "r"(a2), "r"(a3), "r"(b0), "r"(b1));
        }
    }

    // epilogue: bias + relu + fp16, direct half2 stores
    int g = lane >> 2, tid4 = lane & 3;
    #pragma unroll
    for (int nn = 0; nn < 8; nn++) {
        int o = nn * 8 + tid4 * 2;
        float b0f = sB[o], b1f = sB[o + 1];
        int nodeA = node0 + m0 + g;
        if (nodeA < n) {
            float v0 = fmaxf(acc[nn][0] + b0f, 0.f);
            float v1 = fmaxf(acc[nn][1] + b1f, 0.f);
            houth[(size_t)nodeA * 32 + (o >> 1)] = __floats2half2_rn(v0, v1);
        }
        int nodeB = node0 + m0 + 8 + g;
        if (nodeB < n) {
            float v2 = fmaxf(acc[nn][2] + b0f, 0.f);
            float v3 = fmaxf(acc[nn][3] + b1f, 0.f);
            houth[(size_t)nodeB * 32 + (o >> 1)] = __floats2half2_rn(v2, v3);
        }
    }
}

// ---------------- classifier + log_softmax: one warp per node ----------------
__global__ void k_cls(const __half2* __restrict__ h, const float* __restrict__ Wc,
                      const float* __restrict__ bc, float* __restrict__ out, int n) {
    __shared__ float sW[640];
    __shared__ float sb[16];
    int t = threadIdx.x;
    for (int idx = t; idx < 640; idx += 256) sW[idx] = Wc[idx];
    if (t < 10) sb[t] = bc[t];
    __syncthreads();
    int w = (blockIdx.x * blockDim.x + t) >> 5;
    int lane = t & 31;
    if (w >= n) return;
    float2 hv = __half22float2(h[(size_t)w * 32 + lane]);
    float v[10];
    #pragma unroll
    for (int c = 0; c < 10; c++) {
        float p = hv.x * sW[(2 * lane) * 10 + c] + hv.y * sW[(2 * lane + 1) * 10 + c];
        #pragma unroll
        for (int d = 16; d > 0; d >>= 1) p += __shfl_xor_sync(0xffffffffu, p, d);
        v[c] = p + sb[c];
    }
    float m = v[0];
    #pragma unroll
    for (int c = 1; c < 10; c++) m = fmaxf(m, v[c]);
    float s = 0.f;
    #pragma unroll
    for (int c = 0; c < 10; c++) s += expf(v[c] - m);
    float lse = m + logf(s);
    if (lane == 0) {
        #pragma unroll
        for (int c = 0; c < 10; c++) out[(size_t)w * 10 + c] = v[c] - lse;
    }
}

// ---------------- launch ----------------
extern "C" void kernel_launch(void* const* d_in, const int* in_sizes, int n_in,
                              void* d_out, int out_size) {
    const float* x = (const float*)d_in[0];
    const void*  ei = d_in[1];
    int n = in_sizes[0] / HID;
    int e = in_sizes[1] / 2;

    const float* Wl1 = (const float*)d_in[2];
    const float* bl1 = (const float*)d_in[3];
    const float* Wr1 = (const float*)d_in[4];
    const float* Wl2 = (const float*)d_in[5];
    const float* bl2 = (const float*)d_in[6];
    const float* Wr2 = (const float*)d_in[7];
    const float* Wl3 = (const float*)d_in[8];
    const float* bl3 = (const float*)d_in[9];
    const float* Wr3 = (const float*)d_in[10];
    const float* Wc  = (const float*)d_in[11];
    const float* bc  = (const float*)d_in[12];
    float* out = (float*)d_out;

    int *deg, *rowptr, *fill, *bsums, *col;
    float *inv;
    __half2 *xh, *meanh, *h1h, *h2h;
    __half *wf;
    cudaGetSymbolAddress((void**)&deg, g_deg);
    cudaGetSymbolAddress((void**)&rowptr, g_rowptr);
    cudaGetSymbolAddress((void**)&fill, g_fill);
    cudaGetSymbolAddress((void**)&bsums, g_bsums);
    cudaGetSymbolAddress((void**)&col, g_col);
    cudaGetSymbolAddress((void**)&inv, g_inv);
    cudaGetSymbolAddress((void**)&xh, g_xh);
    cudaGetSymbolAddress((void**)&meanh, g_meanh);
    cudaGetSymbolAddress((void**)&h1h, g_h1h);
    cudaGetSymbolAddress((void**)&h2h, g_h2h);
    cudaGetSymbolAddress((void**)&wf, g_wf16);

    cudaFuncSetAttribute(k_gemm, cudaFuncAttributeMaxDynamicSharedMemorySize, GEMM_SMEM);

    // CSR build + conversions
    k_init<<<(n + 255) / 256, 256>>>(deg, n, (const unsigned int*)ei);
    k_count<<<(e + 255) / 256, 256>>>(ei, deg, e);
    int nb = (n + 1023) / 1024;
    k_scan1<<<nb, 1024>>>(deg, rowptr, bsums, n);
    k_scan2<<<1, 128>>>(bsums, nb);
    k_scan3<<<(n + 255) / 256, 256>>>(rowptr, bsums, deg, fill, inv, n, e);
    k_scatter<<<(e + 255) / 256, 256>>>(ei, fill, col, e);
    k_cvt<<<(n * 32 + 255) / 256, 256>>>((const float2*)x, xh, n * 32);
    k_wprep<<<(3 * 64 * 128 + 255) / 256, 256>>>(Wl1, Wr1, Wl2, Wr2, Wl3, Wr3, wf);

    int aggBlocks = (n * 32 + 255) / 256;
    int gemmBlocks = (n + 127) / 128;

    // layer 1
    k_agg<<<aggBlocks, 256>>>(xh, meanh, rowptr, col, inv, n);
    k_gemm<<<gemmBlocks, 256, GEMM_SMEM>>>(meanh, xh, wf, bl1, h1h, n);
    // layer 2
    k_agg<<<aggBlocks, 256>>>(h1h, meanh, rowptr, col, inv, n);
    k_gemm<<<gemmBlocks, 256, GEMM_SMEM>>>(meanh, h1h, wf + 64 * 128, bl2, h2h, n);
    // layer 3
    k_agg<<<aggBlocks, 256>>>(h2h, meanh, rowptr, col, inv, n);
    k_gemm<<<gemmBlocks, 256, GEMM_SMEM>>>(meanh, h2h, wf + 2 * 64 * 128, bl3, h1h, n);
    // classifier
    k_cls<<<(n * 32 + 255) / 256, 256>>>(h1h, Wc, bc, out, n);
}

// round 5
// speedup vs baseline: 1.9209x; 1.1905x over previous
#include <cuda_runtime.h>
#include <cuda_fp16.h>
#include <math.h>

#define NMAX 100000
#define EMAX 1600000
#define HID 64

// ---------------- scratch (static device globals; no allocation) ----------------
__device__ int     g_deg[NMAX];
__device__ int     g_rowptr[NMAX + 1];
__device__ int     g_fill[NMAX];
__device__ int     g_bsums[256];
__device__ float   g_inv[NMAX];
__device__ int     g_col[EMAX];
__device__ __half2 g_xh[(size_t)NMAX * 32];
__device__ __half2 g_meanh[(size_t)NMAX * 32];
__device__ __half2 g_h1h[(size_t)NMAX * 32];
__device__ __half2 g_h2h[(size_t)NMAX * 32];
__device__ __half  g_wf16[3 * 64 * 128];   // [layer][n(64)][k(128)]  k-contig
__device__ int     g_is64;

// ---------------- init: zero deg + detect edge_index dtype ----------------
__global__ void k_init(int* __restrict__ deg, int n, const unsigned int* __restrict__ p) {
    int i = blockIdx.x * blockDim.x + threadIdx.x;
    if (i < n) deg[i] = 0;
    if (i == 0) {
        int ok = 1;
        #pragma unroll
        for (int j = 0; j < 64; j++)
            if (p[2 * j + 1] != 0u) ok = 0;
        g_is64 = ok;
    }
}

__device__ __forceinline__ int load_idx(const void* base, long long i, int is64) {
    if (is64) return (int)((const long long*)base)[i];
    return ((const int*)base)[i];
}

// ---------------- CSR build ----------------
__global__ void k_count(const void* __restrict__ ei, int* __restrict__ deg, int e) {
    int i = blockIdx.x * blockDim.x + threadIdx.x;
    int is64 = g_is64;
    if (i < e) {
        int d = load_idx(ei, (long long)e + i, is64);
        atomicAdd(&deg[d], 1);
    }
}

__global__ void k_scan1(const int* __restrict__ deg, int* __restrict__ rowptr,
                        int* __restrict__ bsums, int n) {
    __shared__ int warp_tot[32];
    int i = blockIdx.x * 1024 + threadIdx.x;
    int lane = threadIdx.x & 31, wid = threadIdx.x >> 5;
    int v = (i < n) ? deg[i] : 0;
    int x = v;
    #pragma unroll
    for (int d = 1; d < 32; d <<= 1) {
        int y = __shfl_up_sync(0xffffffffu, x, d);
        if (lane >= d) x += y;
    }
    if (lane == 31) warp_tot[wid] = x;
    __syncthreads();
    if (wid == 0) {
        int t = warp_tot[lane];
        #pragma unroll
        for (int d = 1; d < 32; d <<= 1) {
            int y = __shfl_up_sync(0xffffffffu, t, d);
            if (lane >= d) t += y;
        }
        warp_tot[lane] = t;
    }
    __syncthreads();
    int base = (wid > 0) ? warp_tot[wid - 1] : 0;
    if (i < n) rowptr[i] = base + x - v;
    if (threadIdx.x == 0) bsums[blockIdx.x] = warp_tot[31];
}

__global__ void k_scan2(int* __restrict__ bsums, int nb) {
    __shared__ int wsum[4];
    int t = threadIdx.x;
    int lane = t & 31, wid = t >> 5;
    int v = (t < nb) ? bsums[t] : 0;
    int x = v;
    #pragma unroll
    for (int d = 1; d < 32; d <<= 1) {
        int y = __shfl_up_sync(0xffffffffu, x, d);
        if (lane >= d) x += y;
    }
    if (lane == 31) wsum[wid] = x;
    __syncthreads();
    int add = 0;
    #pragma unroll
    for (int w = 0; w < 4; w++) if (w < wid) add += wsum[w];
    if (t < nb) bsums[t] = add + x - v;
}

__global__ void k_scan3(int* __restrict__ rowptr, const int* __restrict__ bsums,
                        const int* __restrict__ deg, int* __restrict__ fill,
                        float* __restrict__ inv, int n, int e) {
    int i = blockIdx.x * blockDim.x + threadIdx.x;
    if (i < n) {
        int rp = rowptr[i] + bsums[i >> 10];
        rowptr[i] = rp;
        fill[i] = rp;
        int d = deg[i];
        inv[i] = 1.0f / (float)max(d, 1);
    }
    if (i == 0) rowptr[n] = e;
}

__global__ void k_scatter(const void* __restrict__ ei, int* __restrict__ fill,
                          int* __restrict__ col, int e) {
    int i = blockIdx.x * blockDim.x + threadIdx.x;
    int is64 = g_is64;
    if (i < e) {
        int d = load_idx(ei, (long long)e + i, is64);
        int s = load_idx(ei, (long long)i, is64);
        int p = atomicAdd(&fill[d], 1);
        col[p] = s;
    }
}

// ---------------- convert x (fp32) -> half2 ----------------
__global__ void k_cvt(const float2* __restrict__ x, __half2* __restrict__ xh, int n32) {
    int i = blockIdx.x * blockDim.x + threadIdx.x;
    if (i < n32) {
        float2 v = x[i];
        xh[i] = __floats2half2_rn(v.x, v.y);
    }
}

// ---------------- weight prep: [Wl;Wr] fp32 -> fp16  [layer][n][k] ----------------
__global__ void k_wprep(const float* __restrict__ Wl1, const float* __restrict__ Wr1,
                        const float* __restrict__ Wl2, const float* __restrict__ Wr2,
                        const float* __restrict__ Wl3, const float* __restrict__ Wr3,
                        __half* __restrict__ wf) {
    int i = blockIdx.x * blockDim.x + threadIdx.x;
    if (i >= 3 * 64 * 128) return;
    int layer = i >> 13;
    int rem = i & 8191;
    int nIdx = rem >> 7;
    int k = rem & 127;
    const float* Wl = (layer == 0) ? Wl1 : (layer == 1) ? Wl2 : Wl3;
    const float* Wr = (layer == 0) ? Wr1 : (layer == 1) ? Wr2 : Wr3;
    float v = (k < 64) ? Wl[k * 64 + nIdx] : Wr[(k - 64) * 64 + nIdx];
    wf[i] = __float2half_rn(v);
}

// ---------------- mean aggregation: one warp per node, 8-deep gather unroll ----------------
__global__ void k_agg(const __half2* __restrict__ x, __half2* __restrict__ mean,
                      const int* __restrict__ rowptr, const int* __restrict__ col,
                      const float* __restrict__ inv, int n) {
    int w = (blockIdx.x * blockDim.x + threadIdx.x) >> 5;
    int lane = threadIdx.x & 31;
    if (w >= n) return;
    int s = rowptr[w], e = rowptr[w + 1];
    float ax = 0.f, ay = 0.f;
    int i = s;
    for (; i + 8 <= e; i += 8) {
        int c0 = __ldg(&col[i + 0]); int c1 = __ldg(&col[i + 1]);
        int c2 = __ldg(&col[i + 2]); int c3 = __ldg(&col[i + 3]);
        int c4 = __ldg(&col[i + 4]); int c5 = __ldg(&col[i + 5]);
        int c6 = __ldg(&col[i + 6]); int c7 = __ldg(&col[i + 7]);
        float2 v0 = __half22float2(x[(size_t)c0 * 32 + lane]);
        float2 v1 = __half22float2(x[(size_t)c1 * 32 + lane]);
        float2 v2 = __half22float2(x[(size_t)c2 * 32 + lane]);
        float2 v3 = __half22float2(x[(size_t)c3 * 32 + lane]);
        float2 v4 = __half22float2(x[(size_t)c4 * 32 + lane]);
        float2 v5 = __half22float2(x[(size_t)c5 * 32 + lane]);
        float2 v6 = __half22float2(x[(size_t)c6 * 32 + lane]);
        float2 v7 = __half22float2(x[(size_t)c7 * 32 + lane]);
        ax += ((v0.x + v1.x) + (v2.x + v3.x)) + ((v4.x + v5.x) + (v6.x + v7.x));
        ay += ((v0.y + v1.y) + (v2.y + v3.y)) + ((v4.y + v5.y) + (v6.y + v7.y));
    }
    for (; i + 2 <= e; i += 2) {
        int c0 = __ldg(&col[i]); int c1 = __ldg(&col[i + 1]);
        float2 v0 = __half22float2(x[(size_t)c0 * 32 + lane]);
        float2 v1 = __half22float2(x[(size_t)c1 * 32 + lane]);
        ax += v0.x + v1.x; ay += v0.y + v1.y;
    }
    if (i < e) {
        int c0 = __ldg(&col[i]);
        float2 v0 = __half22float2(x[(size_t)c0 * 32 + lane]);
        ax += v0.x; ay += v0.y;
    }
    float iv = inv[w];
    mean[(size_t)w * 32 + lane] = __floats2half2_rn(ax * iv, ay * iv);
}

// ---------------- tensor-core dual GEMM + bias + ReLU ----------------
#define KPAD 136
#define GEMM_SMEM ((128 * KPAD + 64 * KPAD) * 2 + 256)
#define CLS_SMEM  (GEMM_SMEM + 2560 + 64)

__device__ __forceinline__ void ldsm_x4(unsigned& r0, unsigned& r1, unsigned& r2, unsigned& r3, unsigned addr) {
    asm volatile("ldmatrix.sync.aligned.m8n8.x4.shared.b16 {%0,%1,%2,%3}, [%4];"
                 : "=r"(r0), "=r"(r1), "=r"(r2), "=r"(r3) : "r"(addr));
}
__device__ __forceinline__ void ldsm_x2(unsigned& r0, unsigned& r1, unsigned addr) {
    asm volatile("ldmatrix.sync.aligned.m8n8.x2.shared.b16 {%0,%1}, [%2];"
                 : "=r"(r0), "=r"(r1) : "r"(addr));
}

// shared core: computes acc fragments for 128 nodes x 64 outs
#define GEMM_CORE(meanh, hinh, Wf, bias)                                             \
    __half* sA = smem;                                                               \
    __half* sW = smem + 128 * KPAD;                                                  \
    float*  sB = (float*)(sW + 64 * KPAD);                                           \
    int t = threadIdx.x;                                                             \
    int lane = t & 31, wid = t >> 5;                                                 \
    int node0 = blockIdx.x * 128;                                                    \
    const int4* mean4 = reinterpret_cast<const int4*>(meanh);                        \
    const int4* hin4 = reinterpret_cast<const int4*>(hinh);                          \
    int4* sA4 = reinterpret_cast<int4*>(sA);                                         \
    _Pragma("unroll")                                                                \
    for (int idx = t; idx < 128 * 16; idx += 256) {                                  \
        int nn = idx >> 4, j = idx & 15;                                             \
        int node = node0 + nn;                                                       \
        int4 v = make_int4(0, 0, 0, 0);                                              \
        if (node < n) v = (j < 8) ? mean4[(size_t)node * 8 + j]                      \
                                  : hin4[(size_t)node * 8 + (j - 8)];                \
        sA4[nn * (KPAD / 8) + j] = v;                                                \
    }                                                                                \
    const int4* w4 = reinterpret_cast<const int4*>(Wf);                              \
    int4* sW4 = reinterpret_cast<int4*>(sW);                                         \
    _Pragma("unroll")                                                                \
    for (int idx = t; idx < 64 * 16; idx += 256) {                                   \
        int nn = idx >> 4, j = idx & 15;                                             \
        sW4[nn * (KPAD / 8) + j] = w4[idx];                                          \
    }                                                                                \
    if (t < 64) sB[t] = bias[t];                                                     \
    __syncthreads();                                                                 \
    unsigned sAaddr = (unsigned)__cvta_generic_to_shared(sA);                        \
    unsigned sWaddr = (unsigned)__cvta_generic_to_shared(sW);                        \
    int m0 = wid * 16;                                                               \
    int q = lane >> 3, r = lane & 7;                                                 \
    unsigned aBase = sAaddr + (unsigned)(((m0 + r + ((q & 1) << 3)) * KPAD           \
                                          + ((q >> 1) << 3)) * 2);                   \
    int br = lane & 15;                                                              \
    unsigned bBase = sWaddr + (unsigned)((((br & 7) * KPAD) + ((br >> 3) << 3)) * 2);\
    float acc[8][4];                                                                 \
    _Pragma("unroll")                                                                \
    for (int nn = 0; nn < 8; nn++)                                                   \
        _Pragma("unroll")                                                            \
        for (int j = 0; j < 4; j++) acc[nn][j] = 0.f;                                \
    _Pragma("unroll")                                                                \
    for (int kk = 0; kk < 8; kk++) {                                                 \
        unsigned a0, a1, a2, a3;                                                     \
        ldsm_x4(a0, a1, a2, a3, aBase + kk * 32);                                    \
        _Pragma("unroll")                                                            \
        for (int nn = 0; nn < 8; nn++) {                                             \
            unsigned b0, b1;                                                         \
            ldsm_x2(b0, b1, bBase + (unsigned)((nn * 8 * KPAD + kk * 16) * 2));      \
            asm volatile(                                                            \
                "mma.sync.aligned.m16n8k16.row.col.f32.f16.f16.f32 "                 \
                "{%0,%1,%2,%3}, {%4,%5,%6,%7}, {%8,%9}, {%0,%1,%2,%3};"              \
                : "+f"(acc[nn][0]), "+f"(acc[nn][1]),                                \
                  "+f"(acc[nn][2]), "+f"(acc[nn][3])                                 \
                : "r"(a0), "r"(a1), "r"(a2), "r"(a3), "r"(b0), "r"(b1));             \
        }                                                                            \
    }

__global__ void __launch_bounds__(256) k_gemm(
    const __half2* __restrict__ meanh, const __half2* __restrict__ hinh,
    const __half* __restrict__ Wf, const float* __restrict__ bias,
    __half2* __restrict__ houth, int n) {
    extern __shared__ __half smem[];
    GEMM_CORE(meanh, hinh, Wf, bias)

    int g = lane >> 2, tid4 = lane & 3;
    #pragma unroll
    for (int nn = 0; nn < 8; nn++) {
        int o = nn * 8 + tid4 * 2;
        float b0f = sB[o], b1f = sB[o + 1];
        int nodeA = node0 + m0 + g;
        if (nodeA < n) {
            float v0 = fmaxf(acc[nn][0] + b0f, 0.f);
            float v1 = fmaxf(acc[nn][1] + b1f, 0.f);
            houth[(size_t)nodeA * 32 + (o >> 1)] = __floats2half2_rn(v0, v1);
        }
        int nodeB = node0 + m0 + 8 + g;
        if (nodeB < n) {
            float v2 = fmaxf(acc[nn][2] + b0f, 0.f);
            float v3 = fmaxf(acc[nn][3] + b1f, 0.f);
            houth[(size_t)nodeB * 32 + (o >> 1)] = __floats2half2_rn(v2, v3);
        }
    }
}

// layer 3 fused with classifier + log_softmax (no global h write)
__global__ void __launch_bounds__(256) k_gemm_cls(
    const __half2* __restrict__ meanh, const __half2* __restrict__ hinh,
    const __half* __restrict__ Wf, const float* __restrict__ bias,
    const float* __restrict__ Wc, const float* __restrict__ bc,
    float* __restrict__ out, int n) {
    extern __shared__ __half smem[];
    float* sWc = (float*)(smem + (128 * KPAD + 64 * KPAD)) + 64;  // after sB
    float* sb  = sWc + 640;
    {
        int tt = threadIdx.x;
        for (int idx = tt; idx < 640; idx += 256) sWc[idx] = Wc[idx];
        if (tt < 10) sb[tt] = bc[tt];
    }
    GEMM_CORE(meanh, hinh, Wf, bias)
    __syncthreads();   // all warps done reading sA/sW

    // stage relu(h) into smem (reuse sA region)
    __half2* sH2 = (__half2*)sA;           // [128][32] half2
    float*   sL  = (float*)(sA + 128 * 64); // [128][10] logits
    int g = lane >> 2, tid4 = lane & 3;
    #pragma unroll
    for (int nn = 0; nn < 8; nn++) {
        int o = nn * 8 + tid4 * 2;
        float b0f = sB[o], b1f = sB[o + 1];
        float v0 = fmaxf(acc[nn][0] + b0f, 0.f);
        float v1 = fmaxf(acc[nn][1] + b1f, 0.f);
        sH2[(m0 + g) * 32 + (o >> 1)] = __floats2half2_rn(v0, v1);
        float v2 = fmaxf(acc[nn][2] + b0f, 0.f);
        float v3 = fmaxf(acc[nn][3] + b1f, 0.f);
        sH2[(m0 + 8 + g) * 32 + (o >> 1)] = __floats2half2_rn(v2, v3);
    }
    __syncthreads();

    // logits: 1280 tasks (128 nodes x 10 classes)
    #pragma unroll
    for (int i = 0; i < 5; i++) {
        int task = t + i * 256;
        int node = task / 10;
        int cls = task - node * 10;
        if (node0 + node < n) {
            float a = 0.f;
            #pragma unroll
            for (int k = 0; k < 32; k++) {
                float2 f = __half22float2(sH2[node * 32 + k]);
                a += f.x * sWc[(2 * k) * 10 + cls] + f.y * sWc[(2 * k + 1) * 10 + cls];
            }
            sL[node * 10 + cls] = a + sb[cls];
        }
    }
    __syncthreads();

    // log_softmax: one thread per node
    if (t < 128) {
        int node = node0 + t;
        if (node < n) {
            float v[10];
            #pragma unroll
            for (int c = 0; c < 10; c++) v[c] = sL[t * 10 + c];
            float m = v[0];
            #pragma unroll
            for (int c = 1; c < 10; c++) m = fmaxf(m, v[c]);
            float s = 0.f;
            #pragma unroll
            for (int c = 0; c < 10; c++) s += expf(v[c] - m);
            float lse = m + logf(s);
            #pragma unroll
            for (int c = 0; c < 10; c++) out[(size_t)node * 10 + c] = v[c] - lse;
        }
    }
}

// ---------------- launch ----------------
extern "C" void kernel_launch(void* const* d_in, const int* in_sizes, int n_in,
                              void* d_out, int out_size) {
    const float* x = (const float*)d_in[0];
    const void*  ei = d_in[1];
    int n = in_sizes[0] / HID;
    int e = in_sizes[1] / 2;

    const float* Wl1 = (const float*)d_in[2];
    const float* bl1 = (const float*)d_in[3];
    const float* Wr1 = (const float*)d_in[4];
    const float* Wl2 = (const float*)d_in[5];
    const float* bl2 = (const float*)d_in[6];
    const float* Wr2 = (const float*)d_in[7];
    const float* Wl3 = (const float*)d_in[8];
    const float* bl3 = (const float*)d_in[9];
    const float* Wr3 = (const float*)d_in[10];
    const float* Wc  = (const float*)d_in[11];
    const float* bc  = (const float*)d_in[12];
    float* out = (float*)d_out;

    int *deg, *rowptr, *fill, *bsums, *col;
    float *inv;
    __half2 *xh, *meanh, *h1h, *h2h;
    __half *wf;
    cudaGetSymbolAddress((void**)&deg, g_deg);
    cudaGetSymbolAddress((void**)&rowptr, g_rowptr);
    cudaGetSymbolAddress((void**)&fill, g_fill);
    cudaGetSymbolAddress((void**)&bsums, g_bsums);
    cudaGetSymbolAddress((void**)&col, g_col);
    cudaGetSymbolAddress((void**)&inv, g_inv);
    cudaGetSymbolAddress((void**)&xh, g_xh);
    cudaGetSymbolAddress((void**)&meanh, g_meanh);
    cudaGetSymbolAddress((void**)&h1h, g_h1h);
    cudaGetSymbolAddress((void**)&h2h, g_h2h);
    cudaGetSymbolAddress((void**)&wf, g_wf16);

    cudaFuncSetAttribute(k_gemm, cudaFuncAttributeMaxDynamicSharedMemorySize, GEMM_SMEM);
    cudaFuncSetAttribute(k_gemm_cls, cudaFuncAttributeMaxDynamicSharedMemorySize, CLS_SMEM);

    // CSR build + conversions
    k_init<<<(n + 255) / 256, 256>>>(deg, n, (const unsigned int*)ei);
    k_count<<<(e + 255) / 256, 256>>>(ei, deg, e);
    int nb = (n + 1023) / 1024;
    k_scan1<<<nb, 1024>>>(deg, rowptr, bsums, n);
    k_scan2<<<1, 128>>>(bsums, nb);
    k_scan3<<<(n + 255) / 256, 256>>>(rowptr, bsums, deg, fill, inv, n, e);
    k_scatter<<<(e + 255) / 256, 256>>>(ei, fill, col, e);
    k_cvt<<<(n * 32 + 255) / 256, 256>>>((const float2*)x, xh, n * 32);
    k_wprep<<<(3 * 64 * 128 + 255) / 256, 256>>>(Wl1, Wr1, Wl2, Wr2, Wl3, Wr3, wf);

    int aggBlocks = (n * 32 + 255) / 256;
    int gemmBlocks = (n + 127) / 128;

    // layer 1
    k_agg<<<aggBlocks, 256>>>(xh, meanh, rowptr, col, inv, n);
    k_gemm<<<gemmBlocks, 256, GEMM_SMEM>>>(meanh, xh, wf, bl1, h1h, n);
    // layer 2
    k_agg<<<aggBlocks, 256>>>(h1h, meanh, rowptr, col, inv, n);
    k_gemm<<<gemmBlocks, 256, GEMM_SMEM>>>(meanh, h1h, wf + 64 * 128, bl2, h2h, n);
    // layer 3 + classifier fused
    k_agg<<<aggBlocks, 256>>>(h2h, meanh, rowptr, col, inv, n);
    k_gemm_cls<<<gemmBlocks, 256, CLS_SMEM>>>(meanh, h2h, wf + 2 * 64 * 128, bl3, Wc, bc, out, n);
}

// round 6
// speedup vs baseline: 1.9502x; 1.0153x over previous
#include <cuda_runtime.h>
#include <cuda_fp16.h>
#include <math.h>

#define NMAX 100000
#define EMAX 1600000
#define HID 64

// ---------------- scratch (static device globals; no allocation) ----------------
__device__ int     g_deg[NMAX];
__device__ int     g_rowptr[NMAX + 1];
__device__ int     g_fill[NMAX];
__device__ int     g_bsums[256];
__device__ float   g_inv[NMAX];
__device__ int     g_col[EMAX];
__device__ __half2 g_xh[(size_t)NMAX * 32];
__device__ __half2 g_meanh[(size_t)NMAX * 32];
__device__ __half2 g_h1h[(size_t)NMAX * 32];
__device__ __half2 g_h2h[(size_t)NMAX * 32];
__device__ __half  g_wf16[3 * 64 * 128];   // [layer][n(64)][k(128)]  k-contig

__device__ __forceinline__ int load_idx(const void* base, long long i, int is64) {
    if (is64) return (int)((const long long*)base)[i];
    return ((const int*)base)[i];
}

// per-block edge dtype detection (deterministic, no cross-kernel dependency)
__device__ __forceinline__ int detect_is64(const void* ei, int e) {
    __shared__ int s_is64;
    if (threadIdx.x < 32) {
        const unsigned* p = (const unsigned*)ei;
        int bad = 0;
        int lim = (e > 64) ? 64 : e;
        for (int j = threadIdx.x; j < lim; j += 32) bad |= (p[2 * j + 1] != 0u);
        unsigned m = __ballot_sync(0xffffffffu, bad);
        if (threadIdx.x == 0) s_is64 = (m == 0u);
    }
    __syncthreads();
    return s_is64;
}

// ---------------- prep: zero deg + cvt x->fp16 + pack weights ----------------
__global__ void k_prep(int* __restrict__ deg, int n,
                       const float2* __restrict__ x, __half2* __restrict__ xh,
                       const float* __restrict__ Wl1, const float* __restrict__ Wr1,
                       const float* __restrict__ Wl2, const float* __restrict__ Wr2,
                       const float* __restrict__ Wl3, const float* __restrict__ Wr3,
                       __half* __restrict__ wf) {
    int i = blockIdx.x * blockDim.x + threadIdx.x;
    if (i < n) deg[i] = 0;
    if (i < n * 32) {
        float2 v = x[i];
        xh[i] = __floats2half2_rn(v.x, v.y);
    }
    if (i < 3 * 64 * 128) {
        int layer = i >> 13;
        int rem = i & 8191;
        int nIdx = rem >> 7;
        int k = rem & 127;
        const float* Wl = (layer == 0) ? Wl1 : (layer == 1) ? Wl2 : Wl3;
        const float* Wr = (layer == 0) ? Wr1 : (layer == 1) ? Wr2 : Wr3;
        float v = (k < 64) ? Wl[k * 64 + nIdx] : Wr[(k - 64) * 64 + nIdx];
        wf[i] = __float2half_rn(v);
    }
}

// ---------------- CSR build ----------------
__global__ void k_count(const void* __restrict__ ei, int* __restrict__ deg, int e) {
    int is64 = detect_is64(ei, e);
    int i = blockIdx.x * blockDim.x + threadIdx.x;
    if (i < e) {
        int d = load_idx(ei, (long long)e + i, is64);
        atomicAdd(&deg[d], 1);
    }
}

__global__ void k_scan1(const int* __restrict__ deg, int* __restrict__ rowptr,
                        int* __restrict__ bsums, int n) {
    __shared__ int warp_tot[32];
    int i = blockIdx.x * 1024 + threadIdx.x;
    int lane = threadIdx.x & 31, wid = threadIdx.x >> 5;
    int v = (i < n) ? deg[i] : 0;
    int x = v;
    #pragma unroll
    for (int d = 1; d < 32; d <<= 1) {
        int y = __shfl_up_sync(0xffffffffu, x, d);
        if (lane >= d) x += y;
    }
    if (lane == 31) warp_tot[wid] = x;
    __syncthreads();
    if (wid == 0) {
        int t = warp_tot[lane];
        #pragma unroll
        for (int d = 1; d < 32; d <<= 1) {
            int y = __shfl_up_sync(0xffffffffu, t, d);
            if (lane >= d) t += y;
        }
        warp_tot[lane] = t;
    }
    __syncthreads();
    int base = (wid > 0) ? warp_tot[wid - 1] : 0;
    if (i < n) rowptr[i] = base + x - v;               // exclusive within chunk
    if (threadIdx.x == 0) bsums[blockIdx.x] = warp_tot[31];  // raw chunk total
}

// merged scan2+scan3: each block computes its chunk prefix from raw bsums
__global__ void k_scan23(int* __restrict__ rowptr, const int* __restrict__ bsums,
                         const int* __restrict__ deg, int* __restrict__ fill,
                         float* __restrict__ inv, int n, int e) {
    __shared__ int s_pref;
    int i = blockIdx.x * blockDim.x + threadIdx.x;
    int chunk = (blockIdx.x * blockDim.x) >> 10;   // 256 | 1024 => uniform per block
    if (threadIdx.x < 32) {
        int acc = 0;
        for (int j = threadIdx.x; j < chunk; j += 32) acc += bsums[j];
        #pragma unroll
        for (int d = 16; d > 0; d >>= 1) acc += __shfl_xor_sync(0xffffffffu, acc, d);
        if (threadIdx.x == 0) s_pref = acc;
    }
    __syncthreads();
    if (i < n) {
        int rp = rowptr[i] + s_pref;
        rowptr[i] = rp;
        fill[i] = rp;
        inv[i] = 1.0f / (float)max(deg[i], 1);
    }
    if (i == 0) rowptr[n] = e;
}

__global__ void k_scatter(const void* __restrict__ ei, int* __restrict__ fill,
                          int* __restrict__ col, int e) {
    int is64 = detect_is64(ei, e);
    int i = blockIdx.x * blockDim.x + threadIdx.x;
    if (i < e) {
        int d = load_idx(ei, (long long)e + i, is64);
        int s = load_idx(ei, (long long)i, is64);
        int p = atomicAdd(&fill[d], 1);
        col[p] = s;
    }
}

// ---------------- mean aggregation: one warp per node, 8-deep gather unroll ----------------
__global__ void k_agg(const __half2* __restrict__ x, __half2* __restrict__ mean,
                      const int* __restrict__ rowptr, const int* __restrict__ col,
                      const float* __restrict__ inv, int n) {
    int w = (blockIdx.x * blockDim.x + threadIdx.x) >> 5;
    int lane = threadIdx.x & 31;
    if (w >= n) return;
    int s = rowptr[w], e = rowptr[w + 1];
    float ax = 0.f, ay = 0.f;
    int i = s;
    for (; i + 8 <= e; i += 8) {
        int c0 = __ldg(&col[i + 0]); int c1 = __ldg(&col[i + 1]);
        int c2 = __ldg(&col[i + 2]); int c3 = __ldg(&col[i + 3]);
        int c4 = __ldg(&col[i + 4]); int c5 = __ldg(&col[i + 5]);
        int c6 = __ldg(&col[i + 6]); int c7 = __ldg(&col[i + 7]);
        float2 v0 = __half22float2(x[(size_t)c0 * 32 + lane]);
        float2 v1 = __half22float2(x[(size_t)c1 * 32 + lane]);
        float2 v2 = __half22float2(x[(size_t)c2 * 32 + lane]);
        float2 v3 = __half22float2(x[(size_t)c3 * 32 + lane]);
        float2 v4 = __half22float2(x[(size_t)c4 * 32 + lane]);
        float2 v5 = __half22float2(x[(size_t)c5 * 32 + lane]);
        float2 v6 = __half22float2(x[(size_t)c6 * 32 + lane]);
        float2 v7 = __half22float2(x[(size_t)c7 * 32 + lane]);
        ax += ((v0.x + v1.x) + (v2.x + v3.x)) + ((v4.x + v5.x) + (v6.x + v7.x));
        ay += ((v0.y + v1.y) + (v2.y + v3.y)) + ((v4.y + v5.y) + (v6.y + v7.y));
    }
    for (; i + 2 <= e; i += 2) {
        int c0 = __ldg(&col[i]); int c1 = __ldg(&col[i + 1]);
        float2 v0 = __half22float2(x[(size_t)c0 * 32 + lane]);
        float2 v1 = __half22float2(x[(size_t)c1 * 32 + lane]);
        ax += v0.x + v1.x; ay += v0.y + v1.y;
    }
    if (i < e) {
        int c0 = __ldg(&col[i]);
        float2 v0 = __half22float2(x[(size_t)c0 * 32 + lane]);
        ax += v0.x; ay += v0.y;
    }
    float iv = inv[w];
    mean[(size_t)w * 32 + lane] = __floats2half2_rn(ax * iv, ay * iv);
}

// ---------------- tensor-core dual GEMM + bias + ReLU ----------------
#define KPAD 136
#define GEMM_SMEM ((128 * KPAD + 64 * KPAD) * 2 + 256)
#define CLS_SMEM  (GEMM_SMEM + 2560 + 64)

__device__ __forceinline__ void ldsm_x4(unsigned& r0, unsigned& r1, unsigned& r2, unsigned& r3, unsigned addr) {
    asm volatile("ldmatrix.sync.aligned.m8n8.x4.shared.b16 {%0,%1,%2,%3}, [%4];"
                 : "=r"(r0), "=r"(r1), "=r"(r2), "=r"(r3) : "r"(addr));
}
__device__ __forceinline__ void ldsm_x2(unsigned& r0, unsigned& r1, unsigned addr) {
    asm volatile("ldmatrix.sync.aligned.m8n8.x2.shared.b16 {%0,%1}, [%2];"
                 : "=r"(r0), "=r"(r1) : "r"(addr));
}

#define GEMM_CORE(meanh, hinh, Wf, bias)                                             \
    __half* sA = smem;                                                               \
    __half* sW = smem + 128 * KPAD;                                                  \
    float*  sB = (float*)(sW + 64 * KPAD);                                           \
    int t = threadIdx.x;                                                             \
    int lane = t & 31, wid = t >> 5;                                                 \
    int node0 = blockIdx.x * 128;                                                    \
    const int4* mean4 = reinterpret_cast<const int4*>(meanh);                        \
    const int4* hin4 = reinterpret_cast<const int4*>(hinh);                          \
    int4* sA4 = reinterpret_cast<int4*>(sA);                                         \
    _Pragma("unroll")                                                                \
    for (int idx = t; idx < 128 * 16; idx += 256) {                                  \
        int nn = idx >> 4, j = idx & 15;                                             \
        int node = node0 + nn;                                                       \
        int4 v = make_int4(0, 0, 0, 0);                                              \
        if (node < n) v = (j < 8) ? mean4[(size_t)node * 8 + j]                      \
                                  : hin4[(size_t)node * 8 + (j - 8)];                \
        sA4[nn * (KPAD / 8) + j] = v;                                                \
    }                                                                                \
    const int4* w4 = reinterpret_cast<const int4*>(Wf);                              \
    int4* sW4 = reinterpret_cast<int4*>(sW);                                         \
    _Pragma("unroll")                                                                \
    for (int idx = t; idx < 64 * 16; idx += 256) {                                   \
        int nn = idx >> 4, j = idx & 15;                                             \
        sW4[nn * (KPAD / 8) + j] = w4[idx];                                          \
    }                                                                                \
    if (t < 64) sB[t] = bias[t];                                                     \
    __syncthreads();                                                                 \
    unsigned sAaddr = (unsigned)__cvta_generic_to_shared(sA);                        \
    unsigned sWaddr = (unsigned)__cvta_generic_to_shared(sW);                        \
    int m0 = wid * 16;                                                               \
    int q = lane >> 3, r = lane & 7;                                                 \
    unsigned aBase = sAaddr + (unsigned)(((m0 + r + ((q & 1) << 3)) * KPAD           \
                                          + ((q >> 1) << 3)) * 2);                   \
    int br = lane & 15;                                                              \
    unsigned bBase = sWaddr + (unsigned)((((br & 7) * KPAD) + ((br >> 3) << 3)) * 2);\
    float acc[8][4];                                                                 \
    _Pragma("unroll")                                                                \
    for (int nn = 0; nn < 8; nn++)                                                   \
        _Pragma("unroll")                                                            \
        for (int j = 0; j < 4; j++) acc[nn][j] = 0.f;                                \
    _Pragma("unroll")                                                                \
    for (int kk = 0; kk < 8; kk++) {                                                 \
        unsigned a0, a1, a2, a3;                                                     \
        ldsm_x4(a0, a1, a2, a3, aBase + kk * 32);                                    \
        _Pragma("unroll")                                                            \
        for (int nn = 0; nn < 8; nn++) {                                             \
            unsigned b0, b1;                                                         \
            ldsm_x2(b0, b1, bBase + (unsigned)((nn * 8 * KPAD + kk * 16) * 2));      \
            asm volatile(                                                            \
                "mma.sync.aligned.m16n8k16.row.col.f32.f16.f16.f32 "                 \
                "{%0,%1,%2,%3}, {%4,%5,%6,%7}, {%8,%9}, {%0,%1,%2,%3};"              \
                : "+f"(acc[nn][0]), "+f"(acc[nn][1]),                                \
                  "+f"(acc[nn][2]), "+f"(acc[nn][3])                                 \
                : "r"(a0), "r"(a1), "r"(a2), "r"(a3), "r"(b0), "r"(b1));             \
        }                                                                            \
    }

__global__ void __launch_bounds__(256) k_gemm(
    const __half2* __restrict__ meanh, const __half2* __restrict__ hinh,
    const __half* __restrict__ Wf, const float* __restrict__ bias,
    __half2* __restrict__ houth, int n) {
    extern __shared__ __half smem[];
    GEMM_CORE(meanh, hinh, Wf, bias)

    int g = lane >> 2, tid4 = lane & 3;
    #pragma unroll
    for (int nn = 0; nn < 8; nn++) {
        int o = nn * 8 + tid4 * 2;
        float b0f = sB[o], b1f = sB[o + 1];
        int nodeA = node0 + m0 + g;
        if (nodeA < n) {
            float v0 = fmaxf(acc[nn][0] + b0f, 0.f);
            float v1 = fmaxf(acc[nn][1] + b1f, 0.f);
            houth[(size_t)nodeA * 32 + (o >> 1)] = __floats2half2_rn(v0, v1);
        }
        int nodeB = node0 + m0 + 8 + g;
        if (nodeB < n) {
            float v2 = fmaxf(acc[nn][2] + b0f, 0.f);
            float v3 = fmaxf(acc[nn][3] + b1f, 0.f);
            houth[(size_t)nodeB * 32 + (o >> 1)] = __floats2half2_rn(v2, v3);
        }
    }
}

// layer 3 fused with classifier + log_softmax (no global h write)
__global__ void __launch_bounds__(256) k_gemm_cls(
    const __half2* __restrict__ meanh, const __half2* __restrict__ hinh,
    const __half* __restrict__ Wf, const float* __restrict__ bias,
    const float* __restrict__ Wc, const float* __restrict__ bc,
    float* __restrict__ out, int n) {
    extern __shared__ __half smem[];
    float* sWc = (float*)(smem + (128 * KPAD + 64 * KPAD)) + 64;  // after sB
    float* sb  = sWc + 640;
    {
        int tt = threadIdx.x;
        for (int idx = tt; idx < 640; idx += 256) sWc[idx] = Wc[idx];
        if (tt < 10) sb[tt] = bc[tt];
    }
    GEMM_CORE(meanh, hinh, Wf, bias)
    __syncthreads();   // all warps done reading sA/sW

    __half2* sH2 = (__half2*)sA;            // [128][32] half2
    float*   sL  = (float*)(sA + 128 * 64); // [128][10] logits
    int g = lane >> 2, tid4 = lane & 3;
    #pragma unroll
    for (int nn = 0; nn < 8; nn++) {
        int o = nn * 8 + tid4 * 2;
        float b0f = sB[o], b1f = sB[o + 1];
        float v0 = fmaxf(acc[nn][0] + b0f, 0.f);
        float v1 = fmaxf(acc[nn][1] + b1f, 0.f);
        sH2[(m0 + g) * 32 + (o >> 1)] = __floats2half2_rn(v0, v1);
        float v2 = fmaxf(acc[nn][2] + b0f, 0.f);
        float v3 = fmaxf(acc[nn][3] + b1f, 0.f);
        sH2[(m0 + 8 + g) * 32 + (o >> 1)] = __floats2half2_rn(v2, v3);
    }
    __syncthreads();

    #pragma unroll
    for (int i = 0; i < 5; i++) {
        int task = t + i * 256;
        int node = task / 10;
        int cls = task - node * 10;
        if (node0 + node < n) {
            float a = 0.f;
            #pragma unroll
            for (int k = 0; k < 32; k++) {
                float2 f = __half22float2(sH2[node * 32 + k]);
                a += f.x * sWc[(2 * k) * 10 + cls] + f.y * sWc[(2 * k + 1) * 10 + cls];
            }
            sL[node * 10 + cls] = a + sb[cls];
        }
    }
    __syncthreads();

    if (t < 128) {
        int node = node0 + t;
        if (node < n) {
            float v[10];
            #pragma unroll
            for (int c = 0; c < 10; c++) v[c] = sL[t * 10 + c];
            float m = v[0];
            #pragma unroll
            for (int c = 1; c < 10; c++) m = fmaxf(m, v[c]);
            float s = 0.f;
            #pragma unroll
            for (int c = 0; c < 10; c++) s += expf(v[c] - m);
            float lse = m + logf(s);
            #pragma unroll
            for (int c = 0; c < 10; c++) out[(size_t)node * 10 + c] = v[c] - lse;
        }
    }
}

// ---------------- launch ----------------
extern "C" void kernel_launch(void* const* d_in, const int* in_sizes, int n_in,
                              void* d_out, int out_size) {
    const float* x = (const float*)d_in[0];
    const void*  ei = d_in[1];
    int n = in_sizes[0] / HID;
    int e = in_sizes[1] / 2;

    const float* Wl1 = (const float*)d_in[2];
    const float* bl1 = (const float*)d_in[3];
    const float* Wr1 = (const float*)d_in[4];
    const float* Wl2 = (const float*)d_in[5];
    const float* bl2 = (const float*)d_in[6];
    const float* Wr2 = (const float*)d_in[7];
    const float* Wl3 = (const float*)d_in[8];
    const float* bl3 = (const float*)d_in[9];
    const float* Wr3 = (const float*)d_in[10];
    const float* Wc  = (const float*)d_in[11];
    const float* bc  = (const float*)d_in[12];
    float* out = (float*)d_out;

    int *deg, *rowptr, *fill, *bsums, *col;
    float *inv;
    __half2 *xh, *meanh, *h1h, *h2h;
    __half *wf;
    cudaGetSymbolAddress((void**)&deg, g_deg);
    cudaGetSymbolAddress((void**)&rowptr, g_rowptr);
    cudaGetSymbolAddress((void**)&fill, g_fill);
    cudaGetSymbolAddress((void**)&bsums, g_bsums);
    cudaGetSymbolAddress((void**)&col, g_col);
    cudaGetSymbolAddress((void**)&inv, g_inv);
    cudaGetSymbolAddress((void**)&xh, g_xh);
    cudaGetSymbolAddress((void**)&meanh, g_meanh);
    cudaGetSymbolAddress((void**)&h1h, g_h1h);
    cudaGetSymbolAddress((void**)&h2h, g_h2h);
    cudaGetSymbolAddress((void**)&wf, g_wf16);

    cudaFuncSetAttribute(k_gemm, cudaFuncAttributeMaxDynamicSharedMemorySize, GEMM_SMEM);
    cudaFuncSetAttribute(k_gemm_cls, cudaFuncAttributeMaxDynamicSharedMemorySize, CLS_SMEM);

    // prep + CSR build (10 launches total)
    k_prep<<<(n * 32 + 255) / 256, 256>>>(deg, n, (const float2*)x, xh,
                                          Wl1, Wr1, Wl2, Wr2, Wl3, Wr3, wf);
    k_count<<<(e + 255) / 256, 256>>>(ei, deg, e);
    int nb = (n + 1023) / 1024;
    k_scan1<<<nb, 1024>>>(deg, rowptr, bsums, n);
    k_scan23<<<(n + 255) / 256, 256>>>(rowptr, bsums, deg, fill, inv, n, e);
    k_scatter<<<(e + 255) / 256, 256>>>(ei, fill, col, e);

    int aggBlocks = (n * 32 + 255) / 256;
    int gemmBlocks = (n + 127) / 128;

    // layer 1
    k_agg<<<aggBlocks, 256>>>(xh, meanh, rowptr, col, inv, n);
    k_gemm<<<gemmBlocks, 256, GEMM_SMEM>>>(meanh, xh, wf, bl1, h1h, n);
    // layer 2
    k_agg<<<aggBlocks, 256>>>(h1h, meanh, rowptr, col, inv, n);
    k_gemm<<<gemmBlocks, 256, GEMM_SMEM>>>(meanh, h1h, wf + 64 * 128, bl2, h2h, n);
    // layer 3 + classifier fused
    k_agg<<<aggBlocks, 256>>>(h2h, meanh, rowptr, col, inv, n);
    k_gemm_cls<<<gemmBlocks, 256, CLS_SMEM>>>(meanh, h2h, wf + 2 * 64 * 128, bl3, Wc, bc, out, n);
}